// round 5
// baseline (speedup 1.0000x reference)
#include <cuda_runtime.h>
#include <stdint.h>

// CTC batch loss, prob-domain forward with lazy biased power-of-2 rescaling.
// One CTA (64 threads, 2 warps) per batch element. Warp 0 owns states 0..127,
// warp 1 owns states 128..255 plus state 256; each lane owns 4 states.
// Cross-warp coupling = 1 float/step (state 127) via double-buffered smem + per-step bar.
// Probability rows staged gmem->smem via cp.async in 4-row commit groups (32-row ring).

namespace {
constexpr int kB = 256, kT = 512, kC = 256, kL = 128;
constexpr int kBlank = kC - 1;          // 255
constexpr float kEps = 1e-7f;
constexpr int kDepth = 32;              // smem ring rows (power of 2)
constexpr int kGroup = 4;               // rows per commit group = steps per block
constexpr int kNG    = kT / kGroup;     // 128 groups
constexpr int kPFG   = 7;               // commit groups kept in flight (28 rows)

__device__ __forceinline__ void cp_async16(uint32_t saddr, const float* g) {
    asm volatile("cp.async.cg.shared.global [%0], [%1], 16;" :: "r"(saddr), "l"(g));
}
__device__ __forceinline__ void cp_commit() {
    asm volatile("cp.async.commit_group;" ::: "memory");
}
template <int N>
__device__ __forceinline__ void cp_wait() {
    asm volatile("cp.async.wait_group %0;" :: "n"(N) : "memory");
}
__device__ __forceinline__ uint32_t redux_max_u32(uint32_t v) {
    uint32_t r;
    asm volatile("redux.sync.max.u32 %0, %1, 0xffffffff;" : "=r"(r) : "r"(v));
    return r;
}
} // namespace

__global__ void __launch_bounds__(64) ctc_loss_kernel(
    const int* __restrict__ y_true,     // [B, L] int32, values in [0, C-2]
    const float* __restrict__ y_pred,   // [B, T, C] float32 probabilities
    float* __restrict__ out)            // [B] float32 loss
{
    __shared__ __align__(16) float ring[kDepth][kC];   // 32 KB
    __shared__ float    halo[2];                       // state 127, double-buffered by t&1
    __shared__ uint32_t wmax[2][2];                    // [block parity][warp] max bits

    const int tid = threadIdx.x;
    const int w   = tid >> 5;           // warp: 0 -> states 0..127, 1 -> 128..256
    const int ln  = tid & 31;
    const int b   = blockIdx.x;

    // --- labels: lane owns labels m0 = w*64 + 2*ln and m0+1 ---
    const int m0 = w * 64 + 2 * ln;
    const int2 lab = reinterpret_cast<const int2*>(y_true + (size_t)b * kL)[m0 >> 1];
    const int lab0 = lab.x, lab1 = lab.y;
    const int labm1 = (m0 > 0) ? y_true[(size_t)b * kL + m0 - 1] : -1;
    // skip for odd state s=2m+1: allowed iff m>=1 (s>=2) and label[m] != label[m-1]
    const float sk0 = (m0 > 0 && lab0 != labm1) ? 1.f : 0.f;
    const float sk1 = (lab1 != lab0) ? 1.f : 0.f;

    // --- cp.async staging: each of 64 threads copies 16B of each 1KB row ---
    const float*   gbase = y_pred + (size_t)b * kT * kC + tid * 4;
    const uint32_t sbase = (uint32_t)__cvta_generic_to_shared(&ring[0][0]) + (uint32_t)tid * 16u;

    auto issue_group = [&](int g) {     // 4 rows per commit group
        if (g < kNG) {
#pragma unroll
            for (int j = 0; j < kGroup; j++) {
                int r = g * kGroup + j;
                cp_async16(sbase + (uint32_t)(r & (kDepth - 1)) * (kC * 4),
                           gbase + (size_t)r * kC);
            }
        }
        cp_commit();                    // always commit: wait_group count invariant
    };

    if (tid == 0) {
        halo[0] = 0.f; halo[1] = 0.f;
        wmax[0][0] = 0x3f800000u;       // bits(1.0f): benign first-block scale (2^100)
        wmax[0][1] = 0x3f800000u;
    }

    for (int g = 0; g < kPFG; g++) issue_group(g);

    // alpha regs: a0..a3 = states w*128+4*ln .. +3 ; a4 = state 256 (real only on w1 ln31)
    float a0 = 0.f, a1 = 0.f, a2 = 0.f, a3 = 0.f, a4 = 0.f;
    int   E = 0;                        // true_alpha = stored * 2^E

    float P[kGroup][3];                 // per row: (pb, p_label0, p_label1)
    auto gather = [&](int t_base) {
#pragma unroll
        for (int j = 0; j < kGroup; j++) {
            const float* row = ring[(t_base + j) & (kDepth - 1)];
            P[j][0] = row[kBlank] + kEps;
            P[j][1] = row[lab0]   + kEps;
            P[j][2] = row[lab1]   + kEps;
        }
    };

    // One recurrence step at time t (a bar must precede each call).
    // hsc multiplies the smem halo (rescale frame fix on a block's first step).
    auto step = [&](int t, int j, float hsc) {
        float h1 = __shfl_up_sync(0xffffffffu, a3, 1);   // alpha[base-1] (intra-warp)
        if (ln == 0) h1 = (w == 1) ? halo[t & 1] * hsc : 0.f;
        float t0 = (a0 + h1) * P[j][0];
        float t1 = (a1 + fmaf(sk0, h1, a0)) * P[j][1];
        float t2 = (a2 + a1) * P[j][0];
        float t3 = (a3 + fmaf(sk1, a1, a2)) * P[j][2];
        float t4 = (a4 + a3) * P[j][0];  // state 256 on w1 ln31; bounded junk elsewhere
        a0 = t0; a1 = t1; a2 = t2; a3 = t3; a4 = t4;
        if (w == 0 && ln == 31) halo[(t + 1) & 1] = a3;  // publish state 127 for step t+1
    };

    // Rescale at block g: read both warps' maxes stored at block g-1 (same frame as
    // the current alphas: no scaling happened in between), scale so that max -> 2^100,
    // then store this block's post-scale max for block g+1. Returns the applied scale.
    auto rescale = [&](int g) -> float {
        uint32_t u0 = wmax[(g - 1) & 1][0];
        uint32_t u1 = wmax[(g - 1) & 1][1];
        uint32_t mm = (u0 > u1) ? u0 : u1;               // positive fp32: u32 order-preserving
        int eb   = (int)(mm >> 23);
        int sexp = 227 - eb;                             // scale so max -> 2^100
        if (sexp > 127) sexp = 127;
        float sc = __int_as_float((uint32_t)(sexp + 127) << 23);
        a0 *= sc; a1 *= sc; a2 *= sc; a3 *= sc; a4 *= sc;
        E -= sexp;
        float m = fmaxf(fmaxf(fmaxf(a0, a1), fmaxf(a2, a3)), a4);
        uint32_t mb = redux_max_u32(__float_as_uint(m));
        if (ln == 0) wmax[g & 1][w] = mb;                // visible after next bar
        return sc;
    };

    // ---- block 0: t=0 init + steps 1..3 ----
    cp_wait<kPFG - 1>();
    __syncthreads();                    // also publishes halo/wmax init
    gather(0);
    if (w == 0 && ln == 0) { a0 = P[0][0]; a1 = P[0][1]; }  // only states 0,1 at t=0
    // halo[1] = 0 (init) is exactly a3(t=0) of warp0 lane31.
    step(1, 1, 1.f);
    __syncthreads();
    step(2, 2, 1.f);
    __syncthreads();
    step(3, 3, 1.f);
    issue_group(kPFG);

    // ---- blocks 1..127 ----
#pragma unroll 1
    for (int g = 1; g < kNG; g++) {
        float sc = rescale(g);
        cp_wait<kPFG - 1>();
        __syncthreads();                // publishes halo(step 4g-1), wmax(g), ring group g
        gather(g * kGroup);
        step(4 * g,     0, sc);         // halo written pre-scale -> multiply by sc
        __syncthreads();
        step(4 * g + 1, 1, 1.f);
        __syncthreads();
        step(4 * g + 2, 2, 1.f);
        __syncthreads();
        step(4 * g + 3, 3, 1.f);
        issue_group(g + kPFG);
    }

    // loss = -log(alpha[256] + alpha[255]); both live on warp 1 lane 31.
    if (w == 1 && ln == 31) {
        float tot = a4 + a3;
        out[b] = -(logf(tot) + (float)E * 0.6931471805599453f);
    }
}

extern "C" void kernel_launch(void* const* d_in, const int* in_sizes, int n_in,
                              void* d_out, int out_size) {
    const int* y_true;
    const float* y_pred;
    if (in_sizes[0] == kB * kL) {
        y_true = (const int*)d_in[0];
        y_pred = (const float*)d_in[1];
    } else {
        y_true = (const int*)d_in[1];
        y_pred = (const float*)d_in[0];
    }
    (void)n_in; (void)out_size;
    ctc_loss_kernel<<<kB, 64>>>(y_true, y_pred, (float*)d_out);
}

// round 7
// speedup vs baseline: 1.1571x; 1.1571x over previous
#include <cuda_runtime.h>
#include <stdint.h>

// CTC batch loss, prob-domain forward with lazy biased power-of-2 rescaling.
// One warp per batch element (grid=256, block=32). Lane ln owns states
// [8*ln, 8*ln+8) (lane 31 also owns state 256). Alphas held as f32x2 pairs:
// evens (a0,a2)(a4,a6), odds (a1,a3)(a5,a7); recurrence uses packed
// add/mul/fma.rn.f32x2 (halves FMA-pipe issue). Rows staged via cp.async in
// 4-row commit groups (32-row ring, 8 groups in flight); gathers are
// double-buffered one block ahead so LDS latency hides under compute.
// R7 fix: gather() takes a ROW base — call sites now pass block*kGroup.

namespace {
constexpr int kB = 256, kT = 512, kC = 256, kL = 128;
constexpr int kBlank = kC - 1;          // 255
constexpr float kEps = 1e-7f;
constexpr int kDepth = 32;              // smem ring rows (power of 2)
constexpr int kGroup = 4;               // rows per commit group = steps per block
constexpr int kNG    = kT / kGroup;     // 128 groups

using ull = unsigned long long;

__device__ __forceinline__ void cp_async16(uint32_t saddr, const float* g) {
    asm volatile("cp.async.cg.shared.global [%0], [%1], 16;" :: "r"(saddr), "l"(g));
}
__device__ __forceinline__ void cp_commit() {
    asm volatile("cp.async.commit_group;" ::: "memory");
}
template <int N>
__device__ __forceinline__ void cp_wait() {
    asm volatile("cp.async.wait_group %0;" :: "n"(N) : "memory");
}
__device__ __forceinline__ uint32_t redux_max_u32(uint32_t v) {
    uint32_t r;
    asm volatile("redux.sync.max.u32 %0, %1, 0xffffffff;" : "=r"(r) : "r"(v));
    return r;
}
// f32x2 packed helpers (bit-level pack/unpack are register moves)
__device__ __forceinline__ ull pk2(float lo, float hi) {
    ull r;
    asm("mov.b64 %0, {%1, %2};" : "=l"(r) : "r"(__float_as_uint(lo)), "r"(__float_as_uint(hi)));
    return r;
}
__device__ __forceinline__ void unpk2(ull v, float& lo, float& hi) {
    uint32_t l, h;
    asm("mov.b64 {%0, %1}, %2;" : "=r"(l), "=r"(h) : "l"(v));
    lo = __uint_as_float(l); hi = __uint_as_float(h);
}
__device__ __forceinline__ ull add2(ull a, ull b) {
    ull r; asm("add.rn.f32x2 %0, %1, %2;" : "=l"(r) : "l"(a), "l"(b)); return r;
}
__device__ __forceinline__ ull mul2(ull a, ull b) {
    ull r; asm("mul.rn.f32x2 %0, %1, %2;" : "=l"(r) : "l"(a), "l"(b)); return r;
}
__device__ __forceinline__ ull fma2(ull a, ull b, ull c) {
    ull r; asm("fma.rn.f32x2 %0, %1, %2, %3;" : "=l"(r) : "l"(a), "l"(b), "l"(c)); return r;
}

struct RowP { ull pbb, q13, q57; float pb; };
} // namespace

__global__ void __launch_bounds__(32) ctc_loss_kernel(
    const int* __restrict__ y_true,     // [B, L] int32, values in [0, C-2]
    const float* __restrict__ y_pred,   // [B, T, C] float32 probabilities
    float* __restrict__ out)            // [B] float32 loss
{
    __shared__ __align__(16) float ring[kDepth][kC];   // 32 KB

    const int b  = blockIdx.x;
    const int ln = threadIdx.x;

    // --- labels owned by this lane: indices 4*ln .. 4*ln+3 ---
    const int4 lab4 = reinterpret_cast<const int4*>(y_true + (size_t)b * kL)[ln];
    const int lab0 = lab4.x, lab1 = lab4.y, lab2 = lab4.z, lab3 = lab4.w;
    const int labm1 = __shfl_up_sync(0xffffffffu, lab3, 1);

    // skip for odd state s=2m+1: allowed iff s>=2 and label[m] != label[m-1]
    const float sk0f = (ln > 0 && lab0 != labm1) ? 1.f : 0.f;
    const ull sk01 = pk2(sk0f, (lab1 != lab0) ? 1.f : 0.f);
    const ull sk23 = pk2((lab2 != lab1) ? 1.f : 0.f, (lab3 != lab2) ? 1.f : 0.f);
    const ull eps2 = pk2(kEps, kEps);

    // --- cp.async staging: lane ln copies bytes [32*ln, 32*ln+32) of each 1KB row ---
    const float*   gbase = y_pred + (size_t)b * kT * kC + ln * 8;
    const uint32_t sbase = (uint32_t)__cvta_generic_to_shared(&ring[0][0]) + (uint32_t)ln * 32u;

    auto issue_group = [&](int g) {     // 4 rows per commit group
        if (g < kNG) {
#pragma unroll
            for (int j = 0; j < kGroup; j++) {
                int r = g * kGroup + j;
                uint32_t sa = sbase + (uint32_t)(r & (kDepth - 1)) * (kC * 4);
                const float* ga = gbase + (size_t)r * kC;
                cp_async16(sa, ga);
                cp_async16(sa + 16, ga + 4);
            }
        }
        cp_commit();                    // always commit: wait_group count invariant
    };

    // alphas: e01=(a0,a2) e23=(a4,a6) o01=(a1,a3) o23=(a5,a7); a8 = state 256
    ull e01 = 0, e23 = 0, o01 = 0, o23 = 0;
    float a8 = 0.f;
    int   E = 0;                        // true_alpha = stored * 2^E
    float pendSc = 1.f;                 // scale folded into the NEXT block's first row
    int   pendE = 0;
    int   curSexp = 0;                  // exponent of pendSc (for next measurement)

    RowP PA[kGroup], PB[kGroup];

    auto gather = [&](int t_base, RowP* P) {   // t_base is a ROW index
#pragma unroll
        for (int j = 0; j < kGroup; j++) {
            const float* row = ring[(t_base + j) & (kDepth - 1)];
            float pbv = row[kBlank] + kEps;
            P[j].q13 = add2(pk2(row[lab0], row[lab1]), eps2);
            P[j].q57 = add2(pk2(row[lab2], row[lab3]), eps2);
            P[j].pbb = pk2(pbv, pbv);
            P[j].pb  = pbv;
        }
    };

    auto step = [&](const RowP& r) {
        float a1f, a3f, a5f, a7f;
        unpk2(o01, a1f, a3f);
        unpk2(o23, a5f, a7f);
        float h1 = __shfl_up_sync(0xffffffffu, a7f, 1);   // alpha[8*ln - 1]
        if (ln == 0) h1 = 0.f;
        ull sodd01 = pk2(h1, a1f);        // (a_{-1}, a1)
        ull sodd23 = pk2(a3f, a5f);       // (a3, a5)
        ull in01 = fma2(sk01, sodd01, e01);       // skip-paths for odd states 1,3
        ull in23 = fma2(sk23, sodd23, e23);       // odd states 5,7
        ull ne01 = mul2(add2(e01, sodd01), r.pbb);
        ull ne23 = mul2(add2(e23, sodd23), r.pbb);
        ull no01 = mul2(add2(o01, in01), r.q13);
        ull no23 = mul2(add2(o23, in23), r.q57);
        a8 = (a8 + a7f) * r.pb;           // state 256 (bounded junk on lanes < 31)
        e01 = ne01; e23 = ne23; o01 = no01; o23 = no23;
    };

    // Lazy biased rescale, folded into the block's first-row probabilities:
    // (sc * sum_alpha) * p == sum_alpha * (sc * p), and sc is a power of 2, so this
    // is bit-identical to scaling the alphas directly. Measurement (pre-fold frame)
    // sets the NEXT block's scale: sexp_next = 227 - eb - sexp_being_applied_now.
    auto rescale_fold = [&](RowP* P) {
        ull sc2 = pk2(pendSc, pendSc);
        P[0].pbb = mul2(P[0].pbb, sc2);
        P[0].q13 = mul2(P[0].q13, sc2);
        P[0].q57 = mul2(P[0].q57, sc2);
        P[0].pb *= pendSc;
        E += pendE;
        float x0, x1, x2, x3, y0, y1, y2, y3;
        unpk2(e01, x0, x1); unpk2(e23, x2, x3);
        unpk2(o01, y0, y1); unpk2(o23, y2, y3);
        float m = fmaxf(fmaxf(fmaxf(x0, x1), fmaxf(x2, x3)),
                        fmaxf(fmaxf(y0, y1), fmaxf(y2, fmaxf(y3, a8))));
        uint32_t mm = redux_max_u32(__float_as_uint(m));  // positive fp32: u32 order-preserving
        int eb   = (int)(mm >> 23);
        int sexp = 227 - eb - curSexp;
        if (sexp > 127)  sexp = 127;
        if (sexp < -126) sexp = -126;
        pendSc  = __int_as_float((uint32_t)(sexp + 127) << 23);
        pendE   = -sexp;
        curSexp = sexp;
    };

    // ---- prologue: fill ring (8 groups), gather blocks 0 and 1 ----
    for (int g = 0; g < 8; g++) issue_group(g);
    cp_wait<7>();
    __syncthreads();
    gather(0, PA);                       // rows 0..3  (block 0)
    cp_wait<6>();
    __syncthreads();
    gather(kGroup, PB);                  // rows 4..7  (block 1)

    // ---- block 0: t=0 init + steps 1..3 (data in PA) ----
    if (ln == 0) {
        float q1lo, q1hi;
        unpk2(PA[0].q13, q1lo, q1hi);
        e01 = pk2(PA[0].pb, 0.f);         // alpha0[0] = p_blank
        o01 = pk2(q1lo, 0.f);             // alpha0[1] = p_label0
    }
    step(PA[1]);
    step(PA[2]);
    step(PA[3]);
    issue_group(8);

    // ---- blocks 1..126, ping-pong buffers, gather one block ahead ----
#pragma unroll 1
    for (int g = 1; g < 127; g += 2) {
        // sub-iter g: compute PB (block g), gather block g+1 into PA
        rescale_fold(PB);
        cp_wait<6>();
        __syncthreads();
        gather((g + 1) * kGroup, PA);     // rows 4(g+1) .. 4(g+1)+3
        step(PB[0]); step(PB[1]); step(PB[2]); step(PB[3]);
        issue_group(g + 8);
        // sub-iter g+1: compute PA (block g+1), gather block g+2 into PB
        rescale_fold(PA);
        cp_wait<6>();
        __syncthreads();
        gather((g + 2) * kGroup, PB);     // rows 4(g+2) .. 4(g+2)+3
        step(PA[0]); step(PA[1]); step(PA[2]); step(PA[3]);
        issue_group(g + 9);
    }

    // ---- tail: block 127 (data in PB) ----
    rescale_fold(PB);
    step(PB[0]); step(PB[1]); step(PB[2]); step(PB[3]);

    // loss = -log(alpha[256] + alpha[255]); both live on lane 31.
    if (ln == 31) {
        float a5f, a7f;
        unpk2(o23, a5f, a7f);
        float tot = a8 + a7f;
        out[b] = -(logf(tot) + (float)E * 0.6931471805599453f);
    }
}

extern "C" void kernel_launch(void* const* d_in, const int* in_sizes, int n_in,
                              void* d_out, int out_size) {
    const int* y_true;
    const float* y_pred;
    if (in_sizes[0] == kB * kL) {
        y_true = (const int*)d_in[0];
        y_pred = (const float*)d_in[1];
    } else {
        y_true = (const int*)d_in[1];
        y_pred = (const float*)d_in[0];
    }
    (void)n_in; (void)out_size;
    ctc_loss_kernel<<<kB, 32>>>(y_true, y_pred, (float*)d_out);
}